// round 1
// baseline (speedup 1.0000x reference)
#include <cuda_runtime.h>
#include <math.h>

#define T_STEPS 1024
#define BATCH   512
#define DS      32
#define DC      32
#define DSC     64
#define DY      16
#define DZ      256
#define DH      256
#define RNK     8

#define BT      4      // batch rows per CTA
#define NTHR    256
#define RC      64     // k-rows of WzzT cached in smem

__device__ float g_WzzT[DZ * DZ];

__global__ void transpose_wzz_kernel(const float* __restrict__ Wzz) {
    int idx = blockIdx.x * blockDim.x + threadIdx.x;
    if (idx < DZ * DZ) {
        int k = idx >> 8, j = idx & 255;
        g_WzzT[idx] = Wzz[j * DZ + k];
    }
}

// ---- shared memory layout (float offsets) ----
constexpr int OFF_WZZC  = 0;                       // RC*DZ       = 16384
constexpr int OFF_WZIN  = OFF_WZZC + RC * DZ;      // DSC*DZ      = 16384
constexpr int OFF_WIN   = OFF_WZIN + DSC * DZ;     // DS*DZ       = 8192
constexpr int OFF_WOUT  = OFF_WIN + DS * DZ;       // DZ*DY       = 4096
constexpr int OFF_WZOUT = OFF_WOUT + DZ * DY;      // DZ*RNK      = 2048
constexpr int OFF_VT    = OFF_WZOUT + DZ * RNK;    // DZ*RNK      = 2048
constexpr int OFF_BOUT  = OFF_VT + DZ * RNK;       // 16
constexpr int OFF_BZOUT = OFF_BOUT + DY;           // 8
constexpr int OFF_Z     = OFF_BZOUT + RNK;         // DZ*BT = 1024
constexpr int OFF_TZ    = OFF_Z + DZ * BT;         // 1024
constexpr int OFF_TH    = OFF_TZ + DZ * BT;        // 1024
constexpr int OFF_SC    = OFF_TH + DH * BT;        // DSC*BT = 256
constexpr int OFF_SGP   = OFF_SC + DSC * BT;       // 128 (4 warps x 32 signal partials)
constexpr int OFF_RVP   = OFF_SGP + 128;           // 64  (2 warps x 32 rvec partials)
constexpr int OFF_RS    = OFF_RVP + 64;            // 32  (combined rvec*signal)
constexpr int SMEM_FLOATS = OFF_RS + 32;
constexpr int SMEM_BYTES  = SMEM_FLOATS * 4;       // 210,912 B

// ---- packed f32x2 helpers ----
__device__ __forceinline__ unsigned long long pack2(float x) {
    unsigned long long r;
    asm("mov.b64 %0, {%1, %1};" : "=l"(r) : "f"(x));
    return r;
}
__device__ __forceinline__ void fma2(unsigned long long& d, unsigned long long a,
                                     unsigned long long b) {
    asm("fma.rn.f32x2 %0, %1, %2, %0;" : "+l"(d) : "l"(a), "l"(b));
}
__device__ __forceinline__ float2 unpack2(unsigned long long v) {
    float2 f;
    asm("mov.b64 {%0, %1}, %2;" : "=f"(f.x), "=f"(f.y) : "l"(v));
    return f;
}

__global__ __launch_bounds__(NTHR, 1)
void nmrnn_kernel(const float* __restrict__ s, const float* __restrict__ c,
                  const float* __restrict__ Wzin, const float* __restrict__ bzin,
                  const float* __restrict__ Wzout, const float* __restrict__ bzout,
                  const float* __restrict__ U, const float* __restrict__ V,
                  const float* __restrict__ Win, const float* __restrict__ bin,
                  const float* __restrict__ Wout, const float* __restrict__ bout,
                  float* __restrict__ outp, float* __restrict__ states)
{
    extern __shared__ float sm[];
    const int tid = threadIdx.x;
    const int j = tid;                 // output dim owned by this thread (DZ == DH == NTHR)
    const int b0 = blockIdx.x * BT;
    const int wid = tid >> 5, lane = tid & 31;

    // ---------------- prologue: fill smem (transposed layouts) ----------------
    for (int idx = tid; idx < RC * DZ; idx += NTHR) sm[OFF_WZZC + idx] = g_WzzT[idx];
    for (int idx = tid; idx < DSC * DZ; idx += NTHR) {
        int i = idx >> 8, jj = idx & 255;
        sm[OFF_WZIN + idx] = Wzin[jj * DSC + i];
    }
    for (int idx = tid; idx < DS * DZ; idx += NTHR) {
        int i = idx >> 8, jj = idx & 255;
        sm[OFF_WIN + idx] = Win[jj * DS + i];
    }
    for (int idx = tid; idx < DZ * DY; idx += NTHR) {
        int k = idx >> 4, y = idx & 15;
        sm[OFF_WOUT + idx] = Wout[y * DZ + k];
    }
    for (int idx = tid; idx < DZ * RNK; idx += NTHR) {
        int k = idx >> 3, r = idx & 7;
        sm[OFF_WZOUT + idx] = Wzout[r * DZ + k];
    }
    for (int idx = tid; idx < DZ * RNK; idx += NTHR) sm[OFF_VT + idx] = V[idx];
    if (tid < DY)  sm[OFF_BOUT + tid]  = bout[tid];
    if (tid < RNK) sm[OFF_BZOUT + tid] = bzout[tid];

#pragma unroll
    for (int b = 0; b < BT; b++) {
        sm[OFF_TZ + j * BT + b] = 0.f;
        sm[OFF_TH + j * BT + b] = 0.f;
    }
    if (tid < 64) sm[OFF_RVP + tid] = 0.f;

    float zr[BT], hr[BT];
#pragma unroll
    for (int b = 0; b < BT; b++) { zr[b] = 0.f; hr[b] = 0.f; }

    float Ur[RNK];
#pragma unroll
    for (int r = 0; r < RNK; r++) Ur[r] = U[j * RNK + r];
    const float bzin_j = bzin[j];
    const float bin_j  = bin[j];

    // sc for t = 0: layout sc[i][b]
    {
        int b = tid >> 6, i = tid & 63;
        float v = (i < DS) ? s[((size_t)0 * BATCH + b0 + b) * DS + i]
                           : c[((size_t)0 * BATCH + b0 + b) * DC + (i - DS)];
        sm[OFF_SC + i * BT + b] = v;
    }
    __syncthreads();

    for (int t = 0; t < T_STEPS; t++) {
        // ---------------- phase B: z matvec (packed f32x2) ----------------
        unsigned long long acc01 = pack2(bzin_j);
        unsigned long long acc23 = acc01;
#pragma unroll 8
        for (int i = 0; i < DSC; i++) {
            unsigned long long wp = pack2(sm[OFF_WZIN + i * DZ + j]);
            ulonglong2 sv = *(const ulonglong2*)(sm + OFF_SC + i * BT);
            fma2(acc01, wp, sv.x);
            fma2(acc23, wp, sv.y);
        }
#pragma unroll 8
        for (int k = 0; k < RC; k++) {
            unsigned long long wp = pack2(sm[OFF_WZZC + k * DZ + j]);
            ulonglong2 tv = *(const ulonglong2*)(sm + OFF_TZ + k * BT);
            fma2(acc01, wp, tv.x);
            fma2(acc23, wp, tv.y);
        }
#pragma unroll 16
        for (int k = RC; k < DZ; k++) {
            unsigned long long wp = pack2(__ldg(g_WzzT + k * DZ + j));
            ulonglong2 tv = *(const ulonglong2*)(sm + OFF_TZ + k * BT);
            fma2(acc01, wp, tv.x);
            fma2(acc23, wp, tv.y);
        }
        {
            float2 a01 = unpack2(acc01), a23 = unpack2(acc23);
            float av[BT] = {a01.x, a01.y, a23.x, a23.y};
#pragma unroll
            for (int b = 0; b < BT; b++) {
                zr[b] = 0.99f * zr[b] + 0.01f * av[b];
                sm[OFF_Z + j * BT + b] = zr[b];
                states[((size_t)t * BATCH + b0 + b) * (DZ + DH) + j] = zr[b];
            }
        }
        __syncthreads();  // S1: z ready, tz consumption done

        // ---------------- phase C: tz store, W_in part, signal partials ----------------
#pragma unroll
        for (int b = 0; b < BT; b++) sm[OFF_TZ + j * BT + b] = tanhf(zr[b]);

        unsigned long long hp01 = pack2(bin_j), hp23 = hp01;
#pragma unroll 8
        for (int i = 0; i < DS; i++) {
            unsigned long long wp = pack2(sm[OFF_WIN + i * DZ + j]);
            ulonglong2 sv = *(const ulonglong2*)(sm + OFF_SC + i * BT);
            fma2(hp01, wp, sv.x);
            fma2(hp23, wp, sv.y);
        }
        if (wid < 4) {
            int b = lane >> 3, r = lane & 7;
            float sg = 0.f;
#pragma unroll 8
            for (int k = wid * 64; k < wid * 64 + 64; k++)
                sg += sm[OFF_WZOUT + k * RNK + r] * sm[OFF_Z + k * BT + b];
            sm[OFF_SGP + wid * 32 + lane] = sg;
        }
        __syncthreads();  // S2: signal partials + tz ready

        // ---------------- phase C2: finalize signal, combine with rvec ----------------
        if (tid < 32) {
            int r = tid & 7;
            float x = sm[OFF_SGP + tid] + sm[OFF_SGP + 32 + tid] +
                      sm[OFF_SGP + 64 + tid] + sm[OFF_SGP + 96 + tid] +
                      sm[OFF_BZOUT + r];
            float sg = 1.f / (1.f + expf(-x));
            sm[OFF_RS + tid] = (sm[OFF_RVP + tid] + sm[OFF_RVP + 32 + tid]) * sg;
        }
        __syncthreads();  // S3: rs ready

        // ---------------- phase D: h update ----------------
        {
            float2 h01 = unpack2(hp01), h23 = unpack2(hp23);
            float hp[BT] = {h01.x, h01.y, h23.x, h23.y};
#pragma unroll
            for (int b = 0; b < BT; b++) {
                const float4 r0 = *(const float4*)(sm + OFF_RS + b * 8);
                const float4 r1 = *(const float4*)(sm + OFF_RS + b * 8 + 4);
                float hs = Ur[0] * r0.x + Ur[1] * r0.y + Ur[2] * r0.z + Ur[3] * r0.w +
                           Ur[4] * r1.x + Ur[5] * r1.y + Ur[6] * r1.z + Ur[7] * r1.w;
                hr[b] = 0.9f * hr[b] + 0.1f * (hp[b] + hs);
                states[((size_t)t * BATCH + b0 + b) * (DZ + DH) + DZ + j] = hr[b];
                sm[OFF_TH + j * BT + b] = tanhf(hr[b]);
            }
        }
        __syncthreads();  // S4: th ready

        // ---------------- phase E: rvec partials / outputs / sc prefetch ----------------
        if (wid < 2) {
            int b = lane >> 3, r = lane & 7;
            float ra = 0.f;
#pragma unroll 8
            for (int k = wid * 128; k < wid * 128 + 128; k++)
                ra += sm[OFF_VT + k * RNK + r] * sm[OFF_TH + k * BT + b];
            sm[OFF_RVP + wid * 32 + lane] = ra;
        } else if (wid < 6) {
            int b = wid - 2;
            int y = lane & 15, kh = lane >> 4;
            float oa = 0.f;
#pragma unroll 8
            for (int k = kh * 128; k < kh * 128 + 128; k++)
                oa += sm[OFF_WOUT + k * DY + y] * sm[OFF_TH + k * BT + b];
            oa += __shfl_down_sync(0xffffffffu, oa, 16);
            if (kh == 0)
                outp[((size_t)t * BATCH + b0 + b) * DY + y] = oa + sm[OFF_BOUT + y];
        } else if (t + 1 < T_STEPS) {
#pragma unroll
            for (int rep = 0; rep < 4; rep++) {
                int q = (tid - 192) + rep * 64;
                int b = q >> 6, i = q & 63;
                float v = (i < DS) ? s[((size_t)(t + 1) * BATCH + b0 + b) * DS + i]
                                   : c[((size_t)(t + 1) * BATCH + b0 + b) * DC + (i - DS)];
                sm[OFF_SC + i * BT + b] = v;
            }
        }
        __syncthreads();  // S5: rvec/sc ready for next step
    }
}

extern "C" void kernel_launch(void* const* d_in, const int* in_sizes, int n_in,
                              void* d_out, int out_size) {
    const float* s     = (const float*)d_in[0];
    const float* c     = (const float*)d_in[1];
    const float* Wzz   = (const float*)d_in[2];
    const float* Wzin  = (const float*)d_in[3];
    const float* bzin  = (const float*)d_in[4];
    const float* Wzout = (const float*)d_in[5];
    const float* bzout = (const float*)d_in[6];
    const float* U     = (const float*)d_in[7];
    const float* V     = (const float*)d_in[8];
    const float* Win   = (const float*)d_in[9];
    const float* bin   = (const float*)d_in[10];
    const float* Wout  = (const float*)d_in[11];
    const float* bout  = (const float*)d_in[12];

    float* outp   = (float*)d_out;                               // [T, B, DY]
    float* states = outp + (size_t)T_STEPS * BATCH * DY;         // [T, B, DZ+DH]

    cudaFuncSetAttribute(nmrnn_kernel, cudaFuncAttributeMaxDynamicSharedMemorySize,
                         SMEM_BYTES);

    transpose_wzz_kernel<<<DZ, DZ>>>(Wzz);
    nmrnn_kernel<<<BATCH / BT, NTHR, SMEM_BYTES>>>(
        s, c, Wzin, bzin, Wzout, bzout, U, V, Win, bin, Wout, bout, outp, states);
}

// round 5
// speedup vs baseline: 1.3379x; 1.3379x over previous
#include <cuda_runtime.h>
#include <math.h>

#define T_STEPS 1024
#define BATCH   512
#define DS      32
#define DC      32
#define DSC     64
#define DY      16
#define DZ      256
#define DH      256
#define RNK     8

#define BT      4      // batch rows per CTA
#define NTHR    256
#define RC      80     // k-rows of WzzT cached in smem
#define HREG    (DZ - RC)   // 176 k-rows of WzzT held in registers per thread

__device__ float g_WzzT[DZ * DZ];

__global__ void transpose_wzz_kernel(const float* __restrict__ Wzz) {
    int idx = blockIdx.x * blockDim.x + threadIdx.x;
    if (idx < DZ * DZ) {
        int k = idx >> 8, j = idx & 255;
        g_WzzT[idx] = Wzz[j * DZ + k];
    }
}

// ---- shared memory layout (float offsets) ----
constexpr int OFF_WZZC  = 0;                       // RC*DZ       = 20480
constexpr int OFF_WZIN  = OFF_WZZC + RC * DZ;      // DSC*DZ      = 16384
constexpr int OFF_WIN   = OFF_WZIN + DSC * DZ;     // DS*DZ       = 8192
constexpr int OFF_WOUT  = OFF_WIN + DS * DZ;       // DZ*DY       = 4096
constexpr int OFF_WZOUT = OFF_WOUT + DZ * DY;      // DZ*RNK      = 2048
constexpr int OFF_VT    = OFF_WZOUT + DZ * RNK;    // DZ*RNK      = 2048
constexpr int OFF_BOUT  = OFF_VT + DZ * RNK;       // 16
constexpr int OFF_BZOUT = OFF_BOUT + DY;           // 8
constexpr int OFF_Z     = OFF_BZOUT + RNK;         // DZ*BT = 1024
constexpr int OFF_TZ    = OFF_Z + DZ * BT;         // 1024
constexpr int OFF_TH    = OFF_TZ + DZ * BT;        // 1024
constexpr int OFF_SC    = OFF_TH + DH * BT;        // DSC*BT = 256
constexpr int OFF_SGP   = OFF_SC + DSC * BT;       // 128 (4 warps x 32 signal partials)
constexpr int OFF_RVP   = OFF_SGP + 128;           // 64  (2 warps x 32 rvec partials)
constexpr int OFF_RS    = OFF_RVP + 64;            // 32  (combined rvec*signal)
constexpr int SMEM_FLOATS = OFF_RS + 32;
constexpr int SMEM_BYTES  = SMEM_FLOATS * 4;       // 227,296 B

// ---- packed f32x2 helpers ----
__device__ __forceinline__ unsigned long long pack2(float x) {
    unsigned long long r;
    asm("mov.b64 %0, {%1, %1};" : "=l"(r) : "f"(x));
    return r;
}
__device__ __forceinline__ void fma2(unsigned long long& d, unsigned long long a,
                                     unsigned long long b) {
    asm("fma.rn.f32x2 %0, %1, %2, %0;" : "+l"(d) : "l"(a), "l"(b));
}
__device__ __forceinline__ float2 unpack2(unsigned long long v) {
    float2 f;
    asm("mov.b64 {%0, %1}, %2;" : "=f"(f.x), "=f"(f.y) : "l"(v));
    return f;
}
// ---- hardware tanh (MUFU.TANH, sm_75+) ----
__device__ __forceinline__ float tanha(float x) {
    float y;
    asm("tanh.approx.f32 %0, %1;" : "=f"(y) : "f"(x));
    return y;
}

__global__ __launch_bounds__(NTHR, 1)
void nmrnn_kernel(const float* __restrict__ s, const float* __restrict__ c,
                  const float* __restrict__ Wzin, const float* __restrict__ bzin,
                  const float* __restrict__ Wzout, const float* __restrict__ bzout,
                  const float* __restrict__ U, const float* __restrict__ V,
                  const float* __restrict__ Win, const float* __restrict__ bin,
                  const float* __restrict__ Wout, const float* __restrict__ bout,
                  float* __restrict__ outp, float* __restrict__ states)
{
    extern __shared__ float sm[];
    const int tid = threadIdx.x;
    const int j = tid;                 // output dim owned by this thread (DZ == DH == NTHR)
    const int b0 = blockIdx.x * BT;
    const int wid = tid >> 5, lane = tid & 31;

    // ---------------- prologue: fill smem (transposed layouts) ----------------
    for (int idx = tid; idx < RC * DZ; idx += NTHR) sm[OFF_WZZC + idx] = g_WzzT[idx];
    for (int idx = tid; idx < DSC * DZ; idx += NTHR) {
        int i = idx >> 8, jj = idx & 255;
        sm[OFF_WZIN + idx] = Wzin[jj * DSC + i];
    }
    for (int idx = tid; idx < DS * DZ; idx += NTHR) {
        int i = idx >> 8, jj = idx & 255;
        sm[OFF_WIN + idx] = Win[jj * DS + i];
    }
    for (int idx = tid; idx < DZ * DY; idx += NTHR) {
        int k = idx >> 4, y = idx & 15;
        sm[OFF_WOUT + idx] = Wout[y * DZ + k];
    }
    for (int idx = tid; idx < DZ * RNK; idx += NTHR) {
        int k = idx >> 3, r = idx & 7;
        sm[OFF_WZOUT + idx] = Wzout[r * DZ + k];
    }
    for (int idx = tid; idx < DZ * RNK; idx += NTHR) sm[OFF_VT + idx] = V[idx];
    if (tid < DY)  sm[OFF_BOUT + tid]  = bout[tid];
    if (tid < RNK) sm[OFF_BZOUT + tid] = bzout[tid];

#pragma unroll
    for (int b = 0; b < BT; b++) {
        sm[OFF_TZ + j * BT + b] = 0.f;
        sm[OFF_TH + j * BT + b] = 0.f;
    }
    if (tid < 64) sm[OFF_RVP + tid] = 0.f;

    // ------- register-resident tail of W_zz^T: rows [RC, 256) for column j -------
    float wreg[HREG];
#pragma unroll
    for (int kk = 0; kk < HREG; kk++) wreg[kk] = g_WzzT[(RC + kk) * DZ + j];

    float zr[BT], hr[BT];
#pragma unroll
    for (int b = 0; b < BT; b++) { zr[b] = 0.f; hr[b] = 0.f; }

    float Ur[RNK];
#pragma unroll
    for (int r = 0; r < RNK; r++) Ur[r] = U[j * RNK + r];
    const float bzin_j = bzin[j];
    const float bin_j  = bin[j];

    // sc for t = 0: layout sc[i][b]
    {
        int b = tid >> 6, i = tid & 63;
        float v = (i < DS) ? s[((size_t)0 * BATCH + b0 + b) * DS + i]
                           : c[((size_t)0 * BATCH + b0 + b) * DC + (i - DS)];
        sm[OFF_SC + i * BT + b] = v;
    }
    __syncthreads();

    for (int t = 0; t < T_STEPS; t++) {
        // ---------------- phase B: z matvec (packed f32x2, no global traffic) ----------------
        unsigned long long acc01 = pack2(bzin_j);
        unsigned long long acc23 = acc01;
#pragma unroll 8
        for (int i = 0; i < DSC; i++) {
            unsigned long long wp = pack2(sm[OFF_WZIN + i * DZ + j]);
            ulonglong2 sv = *(const ulonglong2*)(sm + OFF_SC + i * BT);
            fma2(acc01, wp, sv.x);
            fma2(acc23, wp, sv.y);
        }
#pragma unroll 8
        for (int k = 0; k < RC; k++) {
            unsigned long long wp = pack2(sm[OFF_WZZC + k * DZ + j]);
            ulonglong2 tv = *(const ulonglong2*)(sm + OFF_TZ + k * BT);
            fma2(acc01, wp, tv.x);
            fma2(acc23, wp, tv.y);
        }
#pragma unroll
        for (int kk = 0; kk < HREG; kk++) {
            unsigned long long wp = pack2(wreg[kk]);
            ulonglong2 tv = *(const ulonglong2*)(sm + OFF_TZ + (RC + kk) * BT);
            fma2(acc01, wp, tv.x);
            fma2(acc23, wp, tv.y);
        }
        {
            float2 a01 = unpack2(acc01), a23 = unpack2(acc23);
            float av[BT] = {a01.x, a01.y, a23.x, a23.y};
#pragma unroll
            for (int b = 0; b < BT; b++) {
                zr[b] = 0.99f * zr[b] + 0.01f * av[b];
                sm[OFF_Z + j * BT + b] = zr[b];
                __stcs(&states[((size_t)t * BATCH + b0 + b) * (DZ + DH) + j], zr[b]);
            }
        }
        __syncthreads();  // S1: z ready, tz consumption done

        // ---------------- phase C: tz store, W_in part, signal partials ----------------
#pragma unroll
        for (int b = 0; b < BT; b++) sm[OFF_TZ + j * BT + b] = tanha(zr[b]);

        unsigned long long hp01 = pack2(bin_j), hp23 = hp01;
#pragma unroll 8
        for (int i = 0; i < DS; i++) {
            unsigned long long wp = pack2(sm[OFF_WIN + i * DZ + j]);
            ulonglong2 sv = *(const ulonglong2*)(sm + OFF_SC + i * BT);
            fma2(hp01, wp, sv.x);
            fma2(hp23, wp, sv.y);
        }
        if (wid < 4) {
            int b = lane >> 3, r = lane & 7;
            float sg = 0.f;
#pragma unroll 8
            for (int k = wid * 64; k < wid * 64 + 64; k++)
                sg += sm[OFF_WZOUT + k * RNK + r] * sm[OFF_Z + k * BT + b];
            sm[OFF_SGP + wid * 32 + lane] = sg;
        }
        __syncthreads();  // S2: signal partials + tz ready

        // ---------------- phase C2: finalize signal, combine with rvec ----------------
        if (tid < 32) {
            int r = tid & 7;
            float x = sm[OFF_SGP + tid] + sm[OFF_SGP + 32 + tid] +
                      sm[OFF_SGP + 64 + tid] + sm[OFF_SGP + 96 + tid] +
                      sm[OFF_BZOUT + r];
            float sg = 0.5f * (1.f + tanha(0.5f * x));   // sigmoid via MUFU.TANH
            sm[OFF_RS + tid] = (sm[OFF_RVP + tid] + sm[OFF_RVP + 32 + tid]) * sg;
        }
        __syncthreads();  // S3: rs ready

        // ---------------- phase D: h update ----------------
        {
            float2 h01 = unpack2(hp01), h23 = unpack2(hp23);
            float hp[BT] = {h01.x, h01.y, h23.x, h23.y};
#pragma unroll
            for (int b = 0; b < BT; b++) {
                const float4 r0 = *(const float4*)(sm + OFF_RS + b * 8);
                const float4 r1 = *(const float4*)(sm + OFF_RS + b * 8 + 4);
                float hs = Ur[0] * r0.x + Ur[1] * r0.y + Ur[2] * r0.z + Ur[3] * r0.w +
                           Ur[4] * r1.x + Ur[5] * r1.y + Ur[6] * r1.z + Ur[7] * r1.w;
                hr[b] = 0.9f * hr[b] + 0.1f * (hp[b] + hs);
                __stcs(&states[((size_t)t * BATCH + b0 + b) * (DZ + DH) + DZ + j], hr[b]);
                sm[OFF_TH + j * BT + b] = tanha(hr[b]);
            }
        }
        __syncthreads();  // S4: th ready

        // ---------------- phase E: rvec partials / outputs / sc prefetch ----------------
        if (wid < 2) {
            int b = lane >> 3, r = lane & 7;
            float ra = 0.f;
#pragma unroll 8
            for (int k = wid * 128; k < wid * 128 + 128; k++)
                ra += sm[OFF_VT + k * RNK + r] * sm[OFF_TH + k * BT + b];
            sm[OFF_RVP + wid * 32 + lane] = ra;
        } else if (wid < 6) {
            int b = wid - 2;
            int y = lane & 15, kh = lane >> 4;
            float oa = 0.f;
#pragma unroll 8
            for (int k = kh * 128; k < kh * 128 + 128; k++)
                oa += sm[OFF_WOUT + k * DY + y] * sm[OFF_TH + k * BT + b];
            oa += __shfl_down_sync(0xffffffffu, oa, 16);
            if (kh == 0)
                __stcs(&outp[((size_t)t * BATCH + b0 + b) * DY + y], oa + sm[OFF_BOUT + y]);
        } else if (t + 1 < T_STEPS) {
#pragma unroll
            for (int rep = 0; rep < 4; rep++) {
                int q = (tid - 192) + rep * 64;
                int b = q >> 6, i = q & 63;
                float v = (i < DS) ? s[((size_t)(t + 1) * BATCH + b0 + b) * DS + i]
                                   : c[((size_t)(t + 1) * BATCH + b0 + b) * DC + (i - DS)];
                sm[OFF_SC + i * BT + b] = v;
            }
        }
        __syncthreads();  // S5: rvec/sc ready for next step
    }
}

extern "C" void kernel_launch(void* const* d_in, const int* in_sizes, int n_in,
                              void* d_out, int out_size) {
    const float* s     = (const float*)d_in[0];
    const float* c     = (const float*)d_in[1];
    const float* Wzz   = (const float*)d_in[2];
    const float* Wzin  = (const float*)d_in[3];
    const float* bzin  = (const float*)d_in[4];
    const float* Wzout = (const float*)d_in[5];
    const float* bzout = (const float*)d_in[6];
    const float* U     = (const float*)d_in[7];
    const float* V     = (const float*)d_in[8];
    const float* Win   = (const float*)d_in[9];
    const float* bin   = (const float*)d_in[10];
    const float* Wout  = (const float*)d_in[11];
    const float* bout  = (const float*)d_in[12];

    float* outp   = (float*)d_out;                               // [T, B, DY]
    float* states = outp + (size_t)T_STEPS * BATCH * DY;         // [T, B, DZ+DH]

    cudaFuncSetAttribute(nmrnn_kernel, cudaFuncAttributeMaxDynamicSharedMemorySize,
                         SMEM_BYTES);

    transpose_wzz_kernel<<<DZ, DZ>>>(Wzz);
    nmrnn_kernel<<<BATCH / BT, NTHR, SMEM_BYTES>>>(
        s, c, Wzin, bzin, Wzout, bzout, U, V, Win, bin, Wout, bout, outp, states);
}